// round 2
// baseline (speedup 1.0000x reference)
#include <cuda_runtime.h>
#include <math.h>
#include <stdint.h>

// ---------------- constants ----------------
#define B       32
#define H       21
#define W       180
#define PIX     (H*W)              // 3780
#define FEAT    (192*PIX)          // 725760
#define NSPLIT  360
#define KT      (FEAT/NSPLIT)      // 2016
#define DPI     3.14159265358979323846

// ---------------- scratch (device globals; no runtime allocation) ----------------
__device__ float g_x1[B*64*PIX];
__device__ float g_x2[B*64*PIX];
__device__ float g_x3[B*64*PIX];
__device__ float g_x4[B*64*PIX];
__device__ float g_x5[B*128*PIX];
__device__ float g_x6[B*192*PIX];
__device__ float g_wt_in[64*1*25];
__device__ float g_wt1[64*64*25];
__device__ float g_wt2[64*64*25];
__device__ float g_wt3[64*64*25];
__device__ float g_wt4[64*64*25];
__device__ float g_wt5[128*128*25];
__device__ float g_part[4*NSPLIT*32*128];
__device__ float g_h1[B*500];
__device__ float g_h2[B*200];
__device__ float g_h3[B*50];
__device__ float g_phi[64];    // phi[3][21] + phi[63]=dy
__device__ float g_trig[720];  // c1,s1,c2,s2 each [180]

// ---------------- init tables (Hermite basis + Fourier basis) ----------------
__global__ void init_tables(float* phi, float* trig) {
    if (blockIdx.x == 0 && threadIdx.x == 0) {
        double beta = 2.28e-11;
        double L = sqrt(51.0 / beta);
        double spi = sqrt(DPI);
        double n0 = sqrt(spi), n1 = sqrt(2.0 * spi), n2 = sqrt(8.0 * spi);
        for (int i = 0; i < 21; i++) {
            double lat = 20.0 - 2.0 * i;
            double y = lat * 110000.0 / L;
            double e = exp(-y * y / 2.0);
            phi[i]      = (float)(e / n0);
            phi[21 + i] = (float)(e * 2.0 * y / n1);
            phi[42 + i] = (float)(e * (4.0 * y * y - 2.0) / n2);
        }
        phi[63] = (float)(2.0 * 110000.0 / L);   // dy
        for (int n = 0; n < 180; n++) {
            double t = 2.0 * DPI * (double)n / 180.0;
            trig[n]       = (float)cos(t);
            trig[180 + n] = (float)sin(t);
            trig[360 + n] = (float)cos(2.0 * t);
            trig[540 + n] = (float)sin(2.0 * t);
        }
    }
}

// ---------------- weight transpose: [OC][IC][25] -> [IC][25][OC] ----------------
__global__ void transpose_w(const float* __restrict__ w, float* __restrict__ wT,
                            int OC, int IC) {
    int idx = blockIdx.x * blockDim.x + threadIdx.x;
    int tot = OC * IC * 25;
    if (idx >= tot) return;
    int oc = idx / (IC * 25);
    int r  = idx % (IC * 25);
    int ic = r / 25;
    int k  = r % 25;
    wT[(ic * 25 + k) * OC + oc] = w[idx];
}

// ---------------- direct 5x5 SAME conv, register-blocked (XT=30 outputs/thread) -----
template<int IC, int OC, int YR, int ICC>
__global__ __launch_bounds__(OC*YR, 2)
void conv5x5_k(const float* __restrict__ in, const float* __restrict__ wT,
               const float* __restrict__ bias, float* __restrict__ out,
               int outCtot, int ocOff, int doRelu)
{
    constexpr int ROWS = YR + 4;
    constexpr int BT = OC * YR;
    constexpr int XT = 30;
    extern __shared__ float sm[];
    float* sIn = sm;                           // ICC*ROWS*36
    float* sW  = sm + ICC * ROWS * 36;         // ICC*25*OC

    int tid = threadIdx.x;
    int oc = tid % OC;
    int yl = tid / OC;
    int xt = blockIdx.x, yt = blockIdx.y, b = blockIdx.z;
    int x0 = xt * XT, y0 = yt * YR;
    int y = y0 + yl;
    bool valid = (y < H);

    float acc[XT];
#pragma unroll
    for (int j = 0; j < XT; j++) acc[j] = 0.f;

#pragma unroll 1
    for (int ic0 = 0; ic0 < IC; ic0 += ICC) {
        __syncthreads();
        // input tile with zero padding
        for (int i = tid; i < ICC * ROWS * 36; i += BT) {
            int ic = i / (ROWS * 36);
            int r  = (i / 36) % ROWS;
            int xx = i % 36;
            int gy = y0 - 2 + r;
            int gx = x0 - 2 + xx;
            float v = 0.f;
            if (gy >= 0 && gy < H && gx >= 0 && gx < W)
                v = in[((b * IC + ic0 + ic) * H + gy) * W + gx];
            sIn[i] = v;
        }
        // weight chunk (contiguous in transposed layout)
        for (int i = tid; i < ICC * 25 * OC; i += BT)
            sW[i] = wT[ic0 * 25 * OC + i];
        __syncthreads();

        if (valid) {
#pragma unroll 1
            for (int ic = 0; ic < ICC; ic++) {
                float wreg[25];
#pragma unroll
                for (int k = 0; k < 25; k++) wreg[k] = sW[(ic * 25 + k) * OC + oc];
#pragma unroll
                for (int kh = 0; kh < 5; kh++) {
                    const float* row = &sIn[(ic * ROWS + yl + kh) * 36];
#pragma unroll
                    for (int xs3 = 0; xs3 < 3; xs3++) {
                        const int xs = xs3 * 10;
                        float win[14];
#pragma unroll
                        for (int t = 0; t < 14; t++) win[t] = row[xs + t];
#pragma unroll
                        for (int kw = 0; kw < 5; kw++) {
                            float wv = wreg[kh * 5 + kw];
#pragma unroll
                            for (int j = 0; j < 10; j++)
                                acc[xs + j] = fmaf(wv, win[j + kw], acc[xs + j]);
                        }
                    }
                }
            }
        }
    }

    if (valid) {
        float bv = bias[oc];
#pragma unroll
        for (int j = 0; j < XT; j++) {
            float v = acc[j] + bv;
            if (doRelu) v = fmaxf(v, 0.f);
            out[((b * outCtot + ocOff + oc) * H + y) * W + x0 + j] = v;
        }
    }
}

// ---------------- channel-concat copy: src [B,64,PIX] -> dst channel offset --------
__global__ void copy_ch(const float* __restrict__ src, float* __restrict__ dst,
                        int dstCtot, int cOff)
{
    int idx = blockIdx.x * blockDim.x + threadIdx.x;
    if (idx >= B * 64 * PIX) return;
    int p = idx % PIX;
    int c = (idx / PIX) % 64;
    int b = idx / (PIX * 64);
    dst[(b * dstCtot + cOff + c) * PIX + p] = src[idx];
}

// ---------------- Hermite residual along lat (axis y), in place -------------------
__global__ void filter_lat(float* __restrict__ x, const float* __restrict__ phi)
{
    int idx = blockIdx.x * blockDim.x + threadIdx.x;
    if (idx >= B * 192 * W) return;
    int xi = idx % W;
    int c  = (idx / W) % 192;
    int b  = idx / (W * 192);
    float* base = x + (size_t)((b * 192 + c) * H) * W + xi;
    float v[21];
#pragma unroll
    for (int y = 0; y < 21; y++) v[y] = base[y * W];
    float dy = phi[63];
    float u0 = 0.f, u1 = 0.f, u2 = 0.f;
#pragma unroll
    for (int y = 0; y < 21; y++) {
        u0 += v[y] * phi[y];
        u1 += v[y] * phi[21 + y];
        u2 += v[y] * phi[42 + y];
    }
    u0 *= dy; u1 *= dy; u2 *= dy;
#pragma unroll
    for (int y = 0; y < 21; y++)
        base[y * W] = v[y] - (u0 * phi[y] + u1 * phi[21 + y] + u2 * phi[42 + y]);
}

// ---------------- Fourier low-mode residual along lon (k=0,1,2), in place ---------
// Equivalent to: irfft(rfft(x) with coeffs 0..2 zeroed). One warp per 180-row.
__global__ void filter_lon(float* __restrict__ x, const float* __restrict__ trig)
{
    int gw = (blockIdx.x * blockDim.x + threadIdx.x) >> 5;
    int lane = threadIdx.x & 31;
    if (gw >= B * 192 * H) return;
    float* row = x + (size_t)gw * W;
    const float* c1 = trig, *s1 = trig + 180, *c2 = trig + 360, *s2 = trig + 540;
    float v[6];
    float q0 = 0.f, q1 = 0.f, q2 = 0.f, q3 = 0.f, q4 = 0.f;
#pragma unroll
    for (int t = 0; t < 6; t++) {
        int n = t * 32 + lane;
        if (n < W) {
            float xv = row[n];
            v[t] = xv;
            q0 += xv;
            q1 += xv * c1[n];
            q2 += xv * s1[n];
            q3 += xv * c2[n];
            q4 += xv * s2[n];
        }
    }
#pragma unroll
    for (int o = 16; o; o >>= 1) {
        q0 += __shfl_xor_sync(0xffffffffu, q0, o);
        q1 += __shfl_xor_sync(0xffffffffu, q1, o);
        q2 += __shfl_xor_sync(0xffffffffu, q2, o);
        q3 += __shfl_xor_sync(0xffffffffu, q3, o);
        q4 += __shfl_xor_sync(0xffffffffu, q4, o);
    }
    const float inv = 1.f / 180.f, inv2 = 2.f / 180.f;
#pragma unroll
    for (int t = 0; t < 6; t++) {
        int n = t * 32 + lane;
        if (n < W)
            row[n] = v[t] - q0 * inv
                   - inv2 * (q1 * c1[n] + q2 * s1[n] + q3 * c2[n] + q4 * s2[n]);
    }
}

// ---------------- FC1: [32 x 725760] x [500 x 725760]^T, split-K partials ---------
// block: 128 threads, tile 32b x 128j, K chunk KT. Deterministic (no atomics).
__global__ __launch_bounds__(128)
void fc1_partial(const float* __restrict__ act, const float* __restrict__ w,
                 float* __restrict__ part)
{
    __shared__ __align__(16) float As[32 * 36];
    __shared__ __align__(16) float Ws[32 * 132];
    int tid = threadIdx.x;
    int ks = blockIdx.x, jg = blockIdx.y;
    int kb = ks * KT;
    int jg0 = jg * 128;
    int bq = tid & 7, jq = tid >> 3;
    int b0 = bq * 4, j0 = jq * 8;

    float acc[4][8];
#pragma unroll
    for (int i = 0; i < 4; i++)
#pragma unroll
        for (int j = 0; j < 8; j++) acc[i][j] = 0.f;

#pragma unroll 1
    for (int kk = 0; kk < KT; kk += 32) {
        __syncthreads();
#pragma unroll
        for (int r = 0; r < 8; r++) {           // As: 1024 elems, store transposed [k][b]
            int i = tid + r * 128;
            int bb = i >> 5, k = i & 31;
            As[k * 36 + bb] = act[bb * FEAT + kb + kk + k];
        }
#pragma unroll
        for (int r = 0; r < 32; r++) {          // Ws: 4096 elems, store [k][j]
            int i = tid + r * 128;
            int j = i >> 5, k = i & 31;
            int jglob = jg0 + j;
            Ws[k * 132 + j] = (jglob < 500) ? w[(size_t)jglob * FEAT + kb + kk + k] : 0.f;
        }
        __syncthreads();
#pragma unroll 4
        for (int k = 0; k < 32; k++) {
            float4 a  = *reinterpret_cast<const float4*>(&As[k * 36 + b0]);
            float4 w0 = *reinterpret_cast<const float4*>(&Ws[k * 132 + j0]);
            float4 w1 = *reinterpret_cast<const float4*>(&Ws[k * 132 + j0 + 4]);
            float av[4] = {a.x, a.y, a.z, a.w};
            float wv[8] = {w0.x, w0.y, w0.z, w0.w, w1.x, w1.y, w1.z, w1.w};
#pragma unroll
            for (int bb = 0; bb < 4; bb++)
#pragma unroll
                for (int jj = 0; jj < 8; jj++)
                    acc[bb][jj] = fmaf(av[bb], wv[jj], acc[bb][jj]);
        }
    }
#pragma unroll
    for (int bb = 0; bb < 4; bb++)
#pragma unroll
        for (int jj = 0; jj < 8; jj++)
            part[((size_t)(jg * NSPLIT + ks) * 32 + (b0 + bb)) * 128 + j0 + jj] = acc[bb][jj];
}

__global__ void fc1_reduce(const float* __restrict__ part, const float* __restrict__ bias,
                           float* __restrict__ h1)
{
    int idx = blockIdx.x * blockDim.x + threadIdx.x;
    if (idx >= 32 * 512) return;
    int jl = idx & 127;
    int jg = (idx >> 7) & 3;
    int b  = idx >> 9;
    int j = jg * 128 + jl;
    if (j >= 500) return;
    float s = bias[j];
    for (int ks = 0; ks < NSPLIT; ks++)
        s += part[((size_t)(jg * NSPLIT + ks) * 32 + b) * 128 + jl];
    h1[b * 500 + j] = s;    // pre-relu; relu applied when FC2 loads
}

// ---------------- small FC layers ----------------
__global__ void fc_small(const float* __restrict__ in, const float* __restrict__ w,
                         const float* __restrict__ bias, float* __restrict__ out,
                         int N, int K, int reluIn, int reluOut)
{
    int idx = blockIdx.x * blockDim.x + threadIdx.x;
    if (idx >= 32 * N) return;
    int b = idx / N, n = idx % N;
    float s = bias[n];
    const float* ip = in + b * K;
    const float* wp = w + n * K;
    for (int k = 0; k < K; k++) {
        float a = ip[k];
        if (reluIn) a = fmaxf(a, 0.f);
        s = fmaf(a, wp[k], s);
    }
    if (reluOut) s = fmaxf(s, 0.f);
    out[idx] = s;
}

// ---------------- host launcher ----------------
extern "C" void kernel_launch(void* const* d_in, const int* in_sizes, int n_in,
                              void* d_out, int out_size)
{
    const float* x     = (const float*)d_in[0];
    const float* w_in  = (const float*)d_in[1];
    const float* b_in  = (const float*)d_in[2];
    const float* w1    = (const float*)d_in[3];
    const float* b1    = (const float*)d_in[4];
    const float* w2    = (const float*)d_in[5];
    const float* b2    = (const float*)d_in[6];
    const float* w3    = (const float*)d_in[7];
    const float* b3    = (const float*)d_in[8];
    const float* w4    = (const float*)d_in[9];
    const float* b4    = (const float*)d_in[10];
    const float* w5    = (const float*)d_in[11];
    const float* b5    = (const float*)d_in[12];
    const float* wfc1  = (const float*)d_in[13];
    const float* bfc1  = (const float*)d_in[14];
    const float* wfc2  = (const float*)d_in[15];
    const float* bfc2  = (const float*)d_in[16];
    const float* wfc3  = (const float*)d_in[17];
    const float* bfc3  = (const float*)d_in[18];
    const float* wfc4  = (const float*)d_in[19];
    const float* bfc4  = (const float*)d_in[20];
    float* out = (float*)d_out;

    float *x1, *x2, *x3, *x4, *x5, *x6;
    float *wtin, *wt1, *wt2, *wt3, *wt4, *wt5;
    float *part, *h1, *h2, *h3, *phi, *trig;
    cudaGetSymbolAddress((void**)&x1, g_x1);
    cudaGetSymbolAddress((void**)&x2, g_x2);
    cudaGetSymbolAddress((void**)&x3, g_x3);
    cudaGetSymbolAddress((void**)&x4, g_x4);
    cudaGetSymbolAddress((void**)&x5, g_x5);
    cudaGetSymbolAddress((void**)&x6, g_x6);
    cudaGetSymbolAddress((void**)&wtin, g_wt_in);
    cudaGetSymbolAddress((void**)&wt1, g_wt1);
    cudaGetSymbolAddress((void**)&wt2, g_wt2);
    cudaGetSymbolAddress((void**)&wt3, g_wt3);
    cudaGetSymbolAddress((void**)&wt4, g_wt4);
    cudaGetSymbolAddress((void**)&wt5, g_wt5);
    cudaGetSymbolAddress((void**)&part, g_part);
    cudaGetSymbolAddress((void**)&h1, g_h1);
    cudaGetSymbolAddress((void**)&h2, g_h2);
    cudaGetSymbolAddress((void**)&h3, g_h3);
    cudaGetSymbolAddress((void**)&phi, g_phi);
    cudaGetSymbolAddress((void**)&trig, g_trig);

    // opt-in shared memory sizes
    const int smem_in  = (1 * 8 * 36 + 1 * 25 * 64) * 4;     //  7552
    const int smem_64  = (8 * 8 * 36 + 8 * 25 * 64) * 4;     // 60416
    const int smem_128 = (4 * 6 * 36 + 4 * 25 * 128) * 4;    // 54656
    cudaFuncSetAttribute(conv5x5_k<64, 64, 4, 8>,
                         cudaFuncAttributeMaxDynamicSharedMemorySize, smem_64);
    cudaFuncSetAttribute(conv5x5_k<128, 128, 2, 4>,
                         cudaFuncAttributeMaxDynamicSharedMemorySize, smem_128);

    // tables + weight transposes
    init_tables<<<1, 1>>>(phi, trig);
    transpose_w<<<(64 * 1 * 25 + 255) / 256, 256>>>(w_in, wtin, 64, 1);
    transpose_w<<<(64 * 64 * 25 + 255) / 256, 256>>>(w1, wt1, 64, 64);
    transpose_w<<<(64 * 64 * 25 + 255) / 256, 256>>>(w2, wt2, 64, 64);
    transpose_w<<<(64 * 64 * 25 + 255) / 256, 256>>>(w3, wt3, 64, 64);
    transpose_w<<<(64 * 64 * 25 + 255) / 256, 256>>>(w4, wt4, 64, 64);
    transpose_w<<<(128 * 128 * 25 + 255) / 256, 256>>>(w5, wt5, 128, 128);

    dim3 g64(6, 6, B);     // xtiles=6, ytiles=ceil(21/4)=6
    dim3 g128(6, 11, B);   // ytiles=ceil(21/2)=11

    // conv chain (relu fused; concat via channel-offset writes + copies)
    conv5x5_k<1, 64, 4, 1><<<g64, 256, smem_in>>>(x, wtin, b_in, x1, 64, 0, 1);
    conv5x5_k<64, 64, 4, 8><<<g64, 256, smem_64>>>(x1, wt1, b1, x2, 64, 0, 1);
    conv5x5_k<64, 64, 4, 8><<<g64, 256, smem_64>>>(x2, wt2, b2, x3, 64, 0, 1);
    conv5x5_k<64, 64, 4, 8><<<g64, 256, smem_64>>>(x3, wt3, b3, x4, 64, 0, 1);
    conv5x5_k<64, 64, 4, 8><<<g64, 256, smem_64>>>(x4, wt4, b4, x5, 128, 0, 1);
    copy_ch<<<(B * 64 * PIX + 255) / 256, 256>>>(x3, x5, 128, 64);
    conv5x5_k<128, 128, 2, 4><<<g128, 256, smem_128>>>(x5, wt5, b5, x6, 192, 0, 1);
    copy_ch<<<(B * 64 * PIX + 255) / 256, 256>>>(x2, x6, 192, 128);

    // residual filters (closed-form projections; no FFT)
    filter_lat<<<(B * 192 * W + 255) / 256, 256>>>(x6, phi);
    filter_lon<<<(B * 192 * H * 32 + 255) / 256, 256>>>(x6, trig);

    // FC stack
    fc1_partial<<<dim3(NSPLIT, 4), 128>>>(x6, wfc1, part);
    fc1_reduce<<<64, 256>>>(part, bfc1, h1);
    fc_small<<<(32 * 200 + 255) / 256, 256>>>(h1, wfc2, bfc2, h2, 200, 500, 1, 1);
    fc_small<<<(32 * 50 + 255) / 256, 256>>>(h2, wfc3, bfc3, h3, 50, 200, 0, 1);
    fc_small<<<1, 64>>>(h3, wfc4, bfc4, out, 2, 50, 0, 0);
}

// round 3
// speedup vs baseline: 1.0455x; 1.0455x over previous
#include <cuda_runtime.h>
#include <math.h>
#include <stdint.h>

// ---------------- constants ----------------
#define B       32
#define H       21
#define W       180
#define PIX     (H*W)              // 3780
#define FEAT    (192*PIX)          // 725760
#define NSPLIT  360
#define KT      (FEAT/NSPLIT)      // 2016
#define DPI     3.14159265358979323846

// ---------------- scratch (device globals; no runtime allocation) ----------------
__device__ float g_x1[B*64*PIX];
__device__ float g_x2[B*64*PIX];
__device__ float g_x3[B*64*PIX];
__device__ float g_x4[B*64*PIX];
__device__ float g_x5[B*128*PIX];
__device__ float g_x6[B*192*PIX];
__device__ float g_wt_in[64*1*25];
__device__ float g_wt1[64*64*25];
__device__ float g_wt2[64*64*25];
__device__ float g_wt3[64*64*25];
__device__ float g_wt4[64*64*25];
__device__ float g_wt5[128*128*25];
__device__ float g_part[4*NSPLIT*32*128];
__device__ float g_h1[B*500];
__device__ float g_h2[B*200];
__device__ float g_h3[B*50];
__device__ float g_phi[64];    // phi[3][21] + phi[63]=dy
__device__ float g_trig[720];  // c1,s1,c2,s2 each [180]

// ---------------- init tables (Hermite basis + Fourier basis) ----------------
__global__ void init_tables(float* phi, float* trig) {
    if (blockIdx.x == 0 && threadIdx.x == 0) {
        double beta = 2.28e-11;
        double L = sqrt(51.0 / beta);
        double spi = sqrt(DPI);
        double n0 = sqrt(spi), n1 = sqrt(2.0 * spi), n2 = sqrt(8.0 * spi);
        for (int i = 0; i < 21; i++) {
            double lat = 20.0 - 2.0 * i;
            double y = lat * 110000.0 / L;
            double e = exp(-y * y / 2.0);
            phi[i]      = (float)(e / n0);
            phi[21 + i] = (float)(e * 2.0 * y / n1);
            phi[42 + i] = (float)(e * (4.0 * y * y - 2.0) / n2);
        }
        phi[63] = (float)(2.0 * 110000.0 / L);   // dy
        for (int n = 0; n < 180; n++) {
            double t = 2.0 * DPI * (double)n / 180.0;
            trig[n]       = (float)cos(t);
            trig[180 + n] = (float)sin(t);
            trig[360 + n] = (float)cos(2.0 * t);
            trig[540 + n] = (float)sin(2.0 * t);
        }
    }
}

// ---------------- weight transpose: [OC][IC][25] -> [IC][25][OC] ----------------
__global__ void transpose_w(const float* __restrict__ w, float* __restrict__ wT,
                            int OC, int IC) {
    int idx = blockIdx.x * blockDim.x + threadIdx.x;
    int tot = OC * IC * 25;
    if (idx >= tot) return;
    int oc = idx / (IC * 25);
    int r  = idx % (IC * 25);
    int ic = r / 25;
    int k  = r % 25;
    wT[(ic * 25 + k) * OC + oc] = w[idx];
}

// ---------------- direct 5x5 SAME conv, register-blocked (XT=30 outputs/thread) -----
template<int IC, int OC, int YR, int ICC>
__global__ __launch_bounds__(OC*YR, 2)
void conv5x5_k(const float* __restrict__ in, const float* __restrict__ wT,
               const float* __restrict__ bias, float* __restrict__ out,
               int outCtot, int ocOff, int doRelu)
{
    constexpr int ROWS = YR + 4;
    constexpr int BT = OC * YR;
    constexpr int XT = 30;
    extern __shared__ float sm[];
    float* sIn = sm;                           // ICC*ROWS*36
    float* sW  = sm + ICC * ROWS * 36;         // ICC*25*OC

    int tid = threadIdx.x;
    int oc = tid % OC;
    int yl = tid / OC;
    int xt = blockIdx.x, yt = blockIdx.y, b = blockIdx.z;
    int x0 = xt * XT, y0 = yt * YR;
    int y = y0 + yl;
    bool valid = (y < H);

    float acc[XT];
#pragma unroll
    for (int j = 0; j < XT; j++) acc[j] = 0.f;

#pragma unroll 1
    for (int ic0 = 0; ic0 < IC; ic0 += ICC) {
        __syncthreads();
        // input tile with zero padding
        for (int i = tid; i < ICC * ROWS * 36; i += BT) {
            int ic = i / (ROWS * 36);
            int r  = (i / 36) % ROWS;
            int xx = i % 36;
            int gy = y0 - 2 + r;
            int gx = x0 - 2 + xx;
            float v = 0.f;
            if (gy >= 0 && gy < H && gx >= 0 && gx < W)
                v = in[((b * IC + ic0 + ic) * H + gy) * W + gx];
            sIn[i] = v;
        }
        // weight chunk (contiguous in transposed layout)
        for (int i = tid; i < ICC * 25 * OC; i += BT)
            sW[i] = wT[ic0 * 25 * OC + i];
        __syncthreads();

        if (valid) {
#pragma unroll 1
            for (int ic = 0; ic < ICC; ic++) {
                float wreg[25];
#pragma unroll
                for (int k = 0; k < 25; k++) wreg[k] = sW[(ic * 25 + k) * OC + oc];
#pragma unroll
                for (int kh = 0; kh < 5; kh++) {
                    const float* row = &sIn[(ic * ROWS + yl + kh) * 36];
#pragma unroll
                    for (int xs3 = 0; xs3 < 3; xs3++) {
                        const int xs = xs3 * 10;
                        float win[14];
#pragma unroll
                        for (int t = 0; t < 14; t++) win[t] = row[xs + t];
#pragma unroll
                        for (int kw = 0; kw < 5; kw++) {
                            float wv = wreg[kh * 5 + kw];
#pragma unroll
                            for (int j = 0; j < 10; j++)
                                acc[xs + j] = fmaf(wv, win[j + kw], acc[xs + j]);
                        }
                    }
                }
            }
        }
    }

    if (valid) {
        float bv = bias[oc];
#pragma unroll
        for (int j = 0; j < XT; j++) {
            float v = acc[j] + bv;
            if (doRelu) v = fmaxf(v, 0.f);
            out[((b * outCtot + ocOff + oc) * H + y) * W + x0 + j] = v;
        }
    }
}

// ---------------- channel-concat copy: src [B,64,PIX] -> dst channel offset --------
__global__ void copy_ch(const float* __restrict__ src, float* __restrict__ dst,
                        int dstCtot, int cOff)
{
    int idx = blockIdx.x * blockDim.x + threadIdx.x;
    if (idx >= B * 64 * PIX) return;
    int p = idx % PIX;
    int c = (idx / PIX) % 64;
    int b = idx / (PIX * 64);
    dst[(b * dstCtot + cOff + c) * PIX + p] = src[idx];
}

// ---------------- Hermite residual along lat (axis y), in place -------------------
__global__ void filter_lat(float* __restrict__ x, const float* __restrict__ phi)
{
    int idx = blockIdx.x * blockDim.x + threadIdx.x;
    if (idx >= B * 192 * W) return;
    int xi = idx % W;
    int c  = (idx / W) % 192;
    int b  = idx / (W * 192);
    float* base = x + (size_t)((b * 192 + c) * H) * W + xi;
    float v[21];
#pragma unroll
    for (int y = 0; y < 21; y++) v[y] = base[y * W];
    float dy = phi[63];
    float u0 = 0.f, u1 = 0.f, u2 = 0.f;
#pragma unroll
    for (int y = 0; y < 21; y++) {
        u0 += v[y] * phi[y];
        u1 += v[y] * phi[21 + y];
        u2 += v[y] * phi[42 + y];
    }
    u0 *= dy; u1 *= dy; u2 *= dy;
#pragma unroll
    for (int y = 0; y < 21; y++)
        base[y * W] = v[y] - (u0 * phi[y] + u1 * phi[21 + y] + u2 * phi[42 + y]);
}

// ---------------- Fourier low-mode residual along lon (k=0,1,2), in place ---------
// Equivalent to: irfft(rfft(x) with coeffs 0..2 zeroed). One warp per 180-row.
__global__ void filter_lon(float* __restrict__ x, const float* __restrict__ trig)
{
    int gw = (blockIdx.x * blockDim.x + threadIdx.x) >> 5;
    int lane = threadIdx.x & 31;
    if (gw >= B * 192 * H) return;
    float* row = x + (size_t)gw * W;
    const float* c1 = trig, *s1 = trig + 180, *c2 = trig + 360, *s2 = trig + 540;
    float v[6];
    float q0 = 0.f, q1 = 0.f, q2 = 0.f, q3 = 0.f, q4 = 0.f;
#pragma unroll
    for (int t = 0; t < 6; t++) {
        int n = t * 32 + lane;
        if (n < W) {
            float xv = row[n];
            v[t] = xv;
            q0 += xv;
            q1 += xv * c1[n];
            q2 += xv * s1[n];
            q3 += xv * c2[n];
            q4 += xv * s2[n];
        }
    }
#pragma unroll
    for (int o = 16; o; o >>= 1) {
        q0 += __shfl_xor_sync(0xffffffffu, q0, o);
        q1 += __shfl_xor_sync(0xffffffffu, q1, o);
        q2 += __shfl_xor_sync(0xffffffffu, q2, o);
        q3 += __shfl_xor_sync(0xffffffffu, q3, o);
        q4 += __shfl_xor_sync(0xffffffffu, q4, o);
    }
    const float inv = 1.f / 180.f, inv2 = 2.f / 180.f;
#pragma unroll
    for (int t = 0; t < 6; t++) {
        int n = t * 32 + lane;
        if (n < W)
            row[n] = v[t] - q0 * inv
                   - inv2 * (q1 * c1[n] + q2 * s1[n] + q3 * c2[n] + q4 * s2[n]);
    }
}

// ---------------- FC1: [32 x 725760] x [500 x 725760]^T, split-K partials ---------
// block: 128 threads, tile 32b x 128j, K chunk KT. Deterministic (no atomics).
__global__ __launch_bounds__(128)
void fc1_partial(const float* __restrict__ act, const float* __restrict__ w,
                 float* __restrict__ part)
{
    __shared__ __align__(16) float As[32 * 36];
    __shared__ __align__(16) float Ws[32 * 132];
    int tid = threadIdx.x;
    int ks = blockIdx.x, jg = blockIdx.y;
    int kb = ks * KT;
    int jg0 = jg * 128;
    int bq = tid & 7, jq = tid >> 3;
    int b0 = bq * 4, j0 = jq * 8;

    float acc[4][8];
#pragma unroll
    for (int i = 0; i < 4; i++)
#pragma unroll
        for (int j = 0; j < 8; j++) acc[i][j] = 0.f;

#pragma unroll 1
    for (int kk = 0; kk < KT; kk += 32) {
        __syncthreads();
#pragma unroll
        for (int r = 0; r < 8; r++) {           // As: 1024 elems, store transposed [k][b]
            int i = tid + r * 128;
            int bb = i >> 5, k = i & 31;
            As[k * 36 + bb] = act[bb * FEAT + kb + kk + k];
        }
#pragma unroll
        for (int r = 0; r < 32; r++) {          // Ws: 4096 elems, store [k][j]
            int i = tid + r * 128;
            int j = i >> 5, k = i & 31;
            int jglob = jg0 + j;
            Ws[k * 132 + j] = (jglob < 500) ? w[(size_t)jglob * FEAT + kb + kk + k] : 0.f;
        }
        __syncthreads();
#pragma unroll 4
        for (int k = 0; k < 32; k++) {
            float4 a  = *reinterpret_cast<const float4*>(&As[k * 36 + b0]);
            float4 w0 = *reinterpret_cast<const float4*>(&Ws[k * 132 + j0]);
            float4 w1 = *reinterpret_cast<const float4*>(&Ws[k * 132 + j0 + 4]);
            float av[4] = {a.x, a.y, a.z, a.w};
            float wv[8] = {w0.x, w0.y, w0.z, w0.w, w1.x, w1.y, w1.z, w1.w};
#pragma unroll
            for (int bb = 0; bb < 4; bb++)
#pragma unroll
                for (int jj = 0; jj < 8; jj++)
                    acc[bb][jj] = fmaf(av[bb], wv[jj], acc[bb][jj]);
        }
    }
#pragma unroll
    for (int bb = 0; bb < 4; bb++)
#pragma unroll
        for (int jj = 0; jj < 8; jj++)
            part[((size_t)(jg * NSPLIT + ks) * 32 + (b0 + bb)) * 128 + j0 + jj] = acc[bb][jj];
}

__global__ void fc1_reduce(const float* __restrict__ part, const float* __restrict__ bias,
                           float* __restrict__ h1)
{
    int idx = blockIdx.x * blockDim.x + threadIdx.x;
    if (idx >= 32 * 512) return;
    int jl = idx & 127;
    int jg = (idx >> 7) & 3;
    int b  = idx >> 9;
    int j = jg * 128 + jl;
    if (j >= 500) return;
    float s = bias[j];
    for (int ks = 0; ks < NSPLIT; ks++)
        s += part[((size_t)(jg * NSPLIT + ks) * 32 + b) * 128 + jl];
    h1[b * 500 + j] = s;    // pre-relu; relu applied when FC2 loads
}

// ---------------- small FC layers ----------------
__global__ void fc_small(const float* __restrict__ in, const float* __restrict__ w,
                         const float* __restrict__ bias, float* __restrict__ out,
                         int N, int K, int reluIn, int reluOut)
{
    int idx = blockIdx.x * blockDim.x + threadIdx.x;
    if (idx >= 32 * N) return;
    int b = idx / N, n = idx % N;
    float s = bias[n];
    const float* ip = in + b * K;
    const float* wp = w + n * K;
    for (int k = 0; k < K; k++) {
        float a = ip[k];
        if (reluIn) a = fmaxf(a, 0.f);
        s = fmaf(a, wp[k], s);
    }
    if (reluOut) s = fmaxf(s, 0.f);
    out[idx] = s;
}

// ---------------- host launcher ----------------
extern "C" void kernel_launch(void* const* d_in, const int* in_sizes, int n_in,
                              void* d_out, int out_size)
{
    const float* x     = (const float*)d_in[0];
    const float* w_in  = (const float*)d_in[1];
    const float* b_in  = (const float*)d_in[2];
    const float* w1    = (const float*)d_in[3];
    const float* b1    = (const float*)d_in[4];
    const float* w2    = (const float*)d_in[5];
    const float* b2    = (const float*)d_in[6];
    const float* w3    = (const float*)d_in[7];
    const float* b3    = (const float*)d_in[8];
    const float* w4    = (const float*)d_in[9];
    const float* b4    = (const float*)d_in[10];
    const float* w5    = (const float*)d_in[11];
    const float* b5    = (const float*)d_in[12];
    const float* wfc1  = (const float*)d_in[13];
    const float* bfc1  = (const float*)d_in[14];
    const float* wfc2  = (const float*)d_in[15];
    const float* bfc2  = (const float*)d_in[16];
    const float* wfc3  = (const float*)d_in[17];
    const float* bfc3  = (const float*)d_in[18];
    const float* wfc4  = (const float*)d_in[19];
    const float* bfc4  = (const float*)d_in[20];
    float* out = (float*)d_out;

    float *x1, *x2, *x3, *x4, *x5, *x6;
    float *wtin, *wt1, *wt2, *wt3, *wt4, *wt5;
    float *part, *h1, *h2, *h3, *phi, *trig;
    cudaGetSymbolAddress((void**)&x1, g_x1);
    cudaGetSymbolAddress((void**)&x2, g_x2);
    cudaGetSymbolAddress((void**)&x3, g_x3);
    cudaGetSymbolAddress((void**)&x4, g_x4);
    cudaGetSymbolAddress((void**)&x5, g_x5);
    cudaGetSymbolAddress((void**)&x6, g_x6);
    cudaGetSymbolAddress((void**)&wtin, g_wt_in);
    cudaGetSymbolAddress((void**)&wt1, g_wt1);
    cudaGetSymbolAddress((void**)&wt2, g_wt2);
    cudaGetSymbolAddress((void**)&wt3, g_wt3);
    cudaGetSymbolAddress((void**)&wt4, g_wt4);
    cudaGetSymbolAddress((void**)&wt5, g_wt5);
    cudaGetSymbolAddress((void**)&part, g_part);
    cudaGetSymbolAddress((void**)&h1, g_h1);
    cudaGetSymbolAddress((void**)&h2, g_h2);
    cudaGetSymbolAddress((void**)&h3, g_h3);
    cudaGetSymbolAddress((void**)&phi, g_phi);
    cudaGetSymbolAddress((void**)&trig, g_trig);

    // opt-in shared memory sizes
    const int smem_in  = (1 * 8 * 36 + 1 * 25 * 64) * 4;     //  7552
    const int smem_64  = (8 * 8 * 36 + 8 * 25 * 64) * 4;     // 60416
    const int smem_128 = (4 * 6 * 36 + 4 * 25 * 128) * 4;    // 54656
    cudaFuncSetAttribute(conv5x5_k<64, 64, 4, 8>,
                         cudaFuncAttributeMaxDynamicSharedMemorySize, smem_64);
    cudaFuncSetAttribute(conv5x5_k<128, 128, 2, 4>,
                         cudaFuncAttributeMaxDynamicSharedMemorySize, smem_128);

    // tables + weight transposes
    init_tables<<<1, 1>>>(phi, trig);
    transpose_w<<<(64 * 1 * 25 + 255) / 256, 256>>>(w_in, wtin, 64, 1);
    transpose_w<<<(64 * 64 * 25 + 255) / 256, 256>>>(w1, wt1, 64, 64);
    transpose_w<<<(64 * 64 * 25 + 255) / 256, 256>>>(w2, wt2, 64, 64);
    transpose_w<<<(64 * 64 * 25 + 255) / 256, 256>>>(w3, wt3, 64, 64);
    transpose_w<<<(64 * 64 * 25 + 255) / 256, 256>>>(w4, wt4, 64, 64);
    transpose_w<<<(128 * 128 * 25 + 255) / 256, 256>>>(w5, wt5, 128, 128);

    dim3 g64(6, 6, B);     // xtiles=6, ytiles=ceil(21/4)=6
    dim3 g128(6, 11, B);   // ytiles=ceil(21/2)=11

    // conv chain (relu fused; concat via channel-offset writes + copies)
    conv5x5_k<1, 64, 4, 1><<<g64, 256, smem_in>>>(x, wtin, b_in, x1, 64, 0, 1);
    conv5x5_k<64, 64, 4, 8><<<g64, 256, smem_64>>>(x1, wt1, b1, x2, 64, 0, 1);
    conv5x5_k<64, 64, 4, 8><<<g64, 256, smem_64>>>(x2, wt2, b2, x3, 64, 0, 1);
    conv5x5_k<64, 64, 4, 8><<<g64, 256, smem_64>>>(x3, wt3, b3, x4, 64, 0, 1);
    conv5x5_k<64, 64, 4, 8><<<g64, 256, smem_64>>>(x4, wt4, b4, x5, 128, 0, 1);
    copy_ch<<<(B * 64 * PIX + 255) / 256, 256>>>(x3, x5, 128, 64);
    conv5x5_k<128, 128, 2, 4><<<g128, 256, smem_128>>>(x5, wt5, b5, x6, 192, 0, 1);
    copy_ch<<<(B * 64 * PIX + 255) / 256, 256>>>(x2, x6, 192, 128);

    // residual filters (closed-form projections; no FFT)
    filter_lat<<<(B * 192 * W + 255) / 256, 256>>>(x6, phi);
    filter_lon<<<(B * 192 * H * 32 + 255) / 256, 256>>>(x6, trig);

    // FC stack
    fc1_partial<<<dim3(NSPLIT, 4), 128>>>(x6, wfc1, part);
    fc1_reduce<<<64, 256>>>(part, bfc1, h1);
    fc_small<<<(32 * 200 + 255) / 256, 256>>>(h1, wfc2, bfc2, h2, 200, 500, 1, 1);
    fc_small<<<(32 * 50 + 255) / 256, 256>>>(h2, wfc3, bfc3, h3, 50, 200, 0, 1);
    fc_small<<<1, 64>>>(h3, wfc4, bfc4, out, 2, 50, 0, 0);
}

// round 4
// speedup vs baseline: 1.0836x; 1.0364x over previous
#include <cuda_runtime.h>
#include <math.h>
#include <stdint.h>

// ---------------- constants ----------------
#define B       32
#define H       21
#define W       180
#define PIX     (H*W)              // 3780
#define FEAT    (192*PIX)          // 725760
#define NSPLIT  360
#define KT      (FEAT/NSPLIT)      // 2016
#define DPI     3.14159265358979323846

// packed f32x2 FMA (sm_100+): d = a*b + c, lanewise on 2xfp32 in a 64-bit reg
#define FFMA2(d, a, b, c) \
    asm("fma.rn.f32x2 %0, %1, %2, %3;" : "=l"(d) : "l"(a), "l"(b), "l"(c))

// ---------------- scratch (device globals; no runtime allocation) ----------------
__device__ float g_x1[B*64*PIX];
__device__ float g_x2[B*64*PIX];
__device__ float g_x3[B*64*PIX];
__device__ float g_x4[B*64*PIX];
__device__ float g_x5[B*128*PIX];
__device__ float g_x6[B*192*PIX];
__device__ float g_wt_in[64*1*25];     // holds 1*25*32 float2
__device__ float g_wt1[64*64*25];      // holds 64*25*32 float2
__device__ float g_wt2[64*64*25];
__device__ float g_wt3[64*64*25];
__device__ float g_wt4[64*64*25];
__device__ float g_wt5[128*128*25];    // holds 128*25*64 float2
__device__ float g_part[4*NSPLIT*32*128];
__device__ float g_h1[B*500];
__device__ float g_h2[B*200];
__device__ float g_h3[B*50];
__device__ float g_phi[64];    // phi[3][21] + phi[63]=dy
__device__ float g_trig[720];  // c1,s1,c2,s2 each [180]

// ---------------- init tables (Hermite basis + Fourier basis) ----------------
__global__ void init_tables(float* phi, float* trig) {
    if (blockIdx.x == 0 && threadIdx.x == 0) {
        double beta = 2.28e-11;
        double L = sqrt(51.0 / beta);
        double spi = sqrt(DPI);
        double n0 = sqrt(spi), n1 = sqrt(2.0 * spi), n2 = sqrt(8.0 * spi);
        for (int i = 0; i < 21; i++) {
            double lat = 20.0 - 2.0 * i;
            double y = lat * 110000.0 / L;
            double e = exp(-y * y / 2.0);
            phi[i]      = (float)(e / n0);
            phi[21 + i] = (float)(e * 2.0 * y / n1);
            phi[42 + i] = (float)(e * (4.0 * y * y - 2.0) / n2);
        }
        phi[63] = (float)(2.0 * 110000.0 / L);   // dy
        for (int n = 0; n < 180; n++) {
            double t = 2.0 * DPI * (double)n / 180.0;
            trig[n]       = (float)cos(t);
            trig[180 + n] = (float)sin(t);
            trig[360 + n] = (float)cos(2.0 * t);
            trig[540 + n] = (float)sin(2.0 * t);
        }
    }
}

// ---------------- weight pack: [OC][IC][25] -> float2[(ic*25+k)*OCP + p] ----------
// pair .x = oc 2p, .y = oc 2p+1
__global__ void pack_w(const float* __restrict__ w, float2* __restrict__ wP,
                       int OC, int IC) {
    int OCP = OC >> 1;
    int idx = blockIdx.x * blockDim.x + threadIdx.x;
    int tot = IC * 25 * OCP;
    if (idx >= tot) return;
    int p  = idx % OCP;
    int k  = (idx / OCP) % 25;
    int ic = idx / (OCP * 25);
    float2 v;
    v.x = w[(2 * p    ) * IC * 25 + ic * 25 + k];
    v.y = w[(2 * p + 1) * IC * 25 + ic * 25 + k];
    wP[(ic * 25 + k) * OCP + p] = v;
}

// ---------------- 5x5 SAME conv, oc-paired packed f32x2 FMA ----------------------
// Each thread computes 2 output channels (pair p -> oc 2p,2p+1) x 30 pixels.
// Input tile staged in smem pre-duplicated as (v,v) so FFMA2 operands need no packs.
template<int IC, int OCP, int YR, int ICC>
__global__ __launch_bounds__(OCP*YR, 3)
void conv5x5_p(const float* __restrict__ in, const float2* __restrict__ wP,
               const float* __restrict__ bias, float* __restrict__ out,
               int outCtot, float* __restrict__ out2, int out2Ctot, int out2Off)
{
    constexpr int ROWS = YR + 4;
    constexpr int BT = OCP * YR;
    constexpr int XT = 30;
    extern __shared__ char smraw[];
    float2* sIn = (float2*)smraw;                  // ICC*ROWS*36 (duplicated)
    float2* sW  = sIn + ICC * ROWS * 36;           // ICC*25*OCP (oc pairs)

    int tid = threadIdx.x;
    int ocp = tid % OCP;
    int yl = tid / OCP;
    int x0 = blockIdx.x * XT, y0 = blockIdx.y * YR, b = blockIdx.z;
    int y = y0 + yl;
    bool valid = (y < H);

    unsigned long long acc[XT];
#pragma unroll
    for (int j = 0; j < XT; j++) acc[j] = 0ull;

#pragma unroll 1
    for (int ic0 = 0; ic0 < IC; ic0 += ICC) {
        __syncthreads();
        // input tile, zero-padded, value duplicated into both f32x2 lanes
        for (int i = tid; i < ICC * ROWS * 36; i += BT) {
            int ic = i / (ROWS * 36);
            int r  = (i / 36) % ROWS;
            int xx = i % 36;
            int gy = y0 - 2 + r;
            int gx = x0 - 2 + xx;
            float v = 0.f;
            if (gy >= 0 && gy < H && gx >= 0 && gx < W)
                v = in[((b * IC + ic0 + ic) * H + gy) * W + gx];
            sIn[i] = make_float2(v, v);
        }
        // packed weight chunk (contiguous)
        for (int i = tid; i < ICC * 25 * OCP; i += BT)
            sW[i] = wP[ic0 * 25 * OCP + i];
        __syncthreads();

        if (valid) {
#pragma unroll 1
            for (int ic = 0; ic < ICC; ic++) {
#pragma unroll
                for (int kh = 0; kh < 5; kh++) {
                    unsigned long long wp[5];
#pragma unroll
                    for (int kw = 0; kw < 5; kw++)
                        wp[kw] = *reinterpret_cast<const unsigned long long*>(
                            &sW[(ic * 25 + kh * 5 + kw) * OCP + ocp]);
                    const float2* row = &sIn[(ic * ROWS + yl + kh) * 36];
#pragma unroll
                    for (int xs3 = 0; xs3 < 3; xs3++) {
                        const int xs = xs3 * 10;
                        unsigned long long winp[14];
#pragma unroll
                        for (int t = 0; t < 14; t++)
                            winp[t] = *reinterpret_cast<const unsigned long long*>(&row[xs + t]);
#pragma unroll
                        for (int kw = 0; kw < 5; kw++) {
#pragma unroll
                            for (int j = 0; j < 10; j++)
                                FFMA2(acc[xs + j], wp[kw], winp[j + kw], acc[xs + j]);
                        }
                    }
                }
            }
        }
    }

    if (valid) {
        int oc0 = 2 * ocp;
        float bv0 = bias[oc0], bv1 = bias[oc0 + 1];
        float* o0 = out + ((size_t)(b * outCtot + oc0) * H + y) * W + x0;
        float* o1 = o0 + (size_t)H * W;
        float r0[XT], r1[XT];
#pragma unroll
        for (int j = 0; j < XT; j++) {
            float2 v = *reinterpret_cast<float2*>(&acc[j]);
            r0[j] = fmaxf(v.x + bv0, 0.f);
            r1[j] = fmaxf(v.y + bv1, 0.f);
        }
#pragma unroll
        for (int j = 0; j < XT; j += 2) {
            *reinterpret_cast<float2*>(o0 + j) = make_float2(r0[j], r0[j + 1]);
            *reinterpret_cast<float2*>(o1 + j) = make_float2(r1[j], r1[j + 1]);
        }
        if (out2) {
            float* q0 = out2 + ((size_t)(b * out2Ctot + out2Off + oc0) * H + y) * W + x0;
            float* q1 = q0 + (size_t)H * W;
#pragma unroll
            for (int j = 0; j < XT; j += 2) {
                *reinterpret_cast<float2*>(q0 + j) = make_float2(r0[j], r0[j + 1]);
                *reinterpret_cast<float2*>(q1 + j) = make_float2(r1[j], r1[j + 1]);
            }
        }
    }
}

// ---------------- Hermite residual along lat (axis y), in place -------------------
__global__ void filter_lat(float* __restrict__ x, const float* __restrict__ phi)
{
    int idx = blockIdx.x * blockDim.x + threadIdx.x;
    if (idx >= B * 192 * W) return;
    int xi = idx % W;
    int c  = (idx / W) % 192;
    int b  = idx / (W * 192);
    float* base = x + (size_t)((b * 192 + c) * H) * W + xi;
    float v[21];
#pragma unroll
    for (int y = 0; y < 21; y++) v[y] = base[y * W];
    float dy = phi[63];
    float u0 = 0.f, u1 = 0.f, u2 = 0.f;
#pragma unroll
    for (int y = 0; y < 21; y++) {
        u0 += v[y] * phi[y];
        u1 += v[y] * phi[21 + y];
        u2 += v[y] * phi[42 + y];
    }
    u0 *= dy; u1 *= dy; u2 *= dy;
#pragma unroll
    for (int y = 0; y < 21; y++)
        base[y * W] = v[y] - (u0 * phi[y] + u1 * phi[21 + y] + u2 * phi[42 + y]);
}

// ---------------- Fourier low-mode residual along lon (k=0,1,2), in place ---------
__global__ void filter_lon(float* __restrict__ x, const float* __restrict__ trig)
{
    int gw = (blockIdx.x * blockDim.x + threadIdx.x) >> 5;
    int lane = threadIdx.x & 31;
    if (gw >= B * 192 * H) return;
    float* row = x + (size_t)gw * W;
    const float* c1 = trig, *s1 = trig + 180, *c2 = trig + 360, *s2 = trig + 540;
    float v[6];
    float q0 = 0.f, q1 = 0.f, q2 = 0.f, q3 = 0.f, q4 = 0.f;
#pragma unroll
    for (int t = 0; t < 6; t++) {
        int n = t * 32 + lane;
        if (n < W) {
            float xv = row[n];
            v[t] = xv;
            q0 += xv;
            q1 += xv * c1[n];
            q2 += xv * s1[n];
            q3 += xv * c2[n];
            q4 += xv * s2[n];
        }
    }
#pragma unroll
    for (int o = 16; o; o >>= 1) {
        q0 += __shfl_xor_sync(0xffffffffu, q0, o);
        q1 += __shfl_xor_sync(0xffffffffu, q1, o);
        q2 += __shfl_xor_sync(0xffffffffu, q2, o);
        q3 += __shfl_xor_sync(0xffffffffu, q3, o);
        q4 += __shfl_xor_sync(0xffffffffu, q4, o);
    }
    const float inv = 1.f / 180.f, inv2 = 2.f / 180.f;
#pragma unroll
    for (int t = 0; t < 6; t++) {
        int n = t * 32 + lane;
        if (n < W)
            row[n] = v[t] - q0 * inv
                   - inv2 * (q1 * c1[n] + q2 * s1[n] + q3 * c2[n] + q4 * s2[n]);
    }
}

// ---------------- FC1: [32 x 725760] x [500 x 725760]^T, split-K partials ---------
__global__ __launch_bounds__(128)
void fc1_partial(const float* __restrict__ act, const float* __restrict__ w,
                 float* __restrict__ part)
{
    __shared__ __align__(16) float As[32 * 36];
    __shared__ __align__(16) float Ws[32 * 132];
    int tid = threadIdx.x;
    int ks = blockIdx.x, jg = blockIdx.y;
    int kb = ks * KT;
    int jg0 = jg * 128;
    int bq = tid & 7, jq = tid >> 3;
    int b0 = bq * 4, j0 = jq * 8;

    float acc[4][8];
#pragma unroll
    for (int i = 0; i < 4; i++)
#pragma unroll
        for (int j = 0; j < 8; j++) acc[i][j] = 0.f;

#pragma unroll 1
    for (int kk = 0; kk < KT; kk += 32) {
        __syncthreads();
#pragma unroll
        for (int r = 0; r < 8; r++) {
            int i = tid + r * 128;
            int bb = i >> 5, k = i & 31;
            As[k * 36 + bb] = act[bb * FEAT + kb + kk + k];
        }
#pragma unroll
        for (int r = 0; r < 32; r++) {
            int i = tid + r * 128;
            int j = i >> 5, k = i & 31;
            int jglob = jg0 + j;
            Ws[k * 132 + j] = (jglob < 500) ? w[(size_t)jglob * FEAT + kb + kk + k] : 0.f;
        }
        __syncthreads();
#pragma unroll 4
        for (int k = 0; k < 32; k++) {
            float4 a  = *reinterpret_cast<const float4*>(&As[k * 36 + b0]);
            float4 w0 = *reinterpret_cast<const float4*>(&Ws[k * 132 + j0]);
            float4 w1 = *reinterpret_cast<const float4*>(&Ws[k * 132 + j0 + 4]);
            float av[4] = {a.x, a.y, a.z, a.w};
            float wv[8] = {w0.x, w0.y, w0.z, w0.w, w1.x, w1.y, w1.z, w1.w};
#pragma unroll
            for (int bb = 0; bb < 4; bb++)
#pragma unroll
                for (int jj = 0; jj < 8; jj++)
                    acc[bb][jj] = fmaf(av[bb], wv[jj], acc[bb][jj]);
        }
    }
#pragma unroll
    for (int bb = 0; bb < 4; bb++)
#pragma unroll
        for (int jj = 0; jj < 8; jj++)
            part[((size_t)(jg * NSPLIT + ks) * 32 + (b0 + bb)) * 128 + j0 + jj] = acc[bb][jj];
}

__global__ void fc1_reduce(const float* __restrict__ part, const float* __restrict__ bias,
                           float* __restrict__ h1)
{
    int idx = blockIdx.x * blockDim.x + threadIdx.x;
    if (idx >= 32 * 512) return;
    int jl = idx & 127;
    int jg = (idx >> 7) & 3;
    int b  = idx >> 9;
    int j = jg * 128 + jl;
    if (j >= 500) return;
    float s = bias[j];
    for (int ks = 0; ks < NSPLIT; ks++)
        s += part[((size_t)(jg * NSPLIT + ks) * 32 + b) * 128 + jl];
    h1[b * 500 + j] = s;    // pre-relu; relu applied when FC2 loads
}

// ---------------- small FC layers ----------------
__global__ void fc_small(const float* __restrict__ in, const float* __restrict__ w,
                         const float* __restrict__ bias, float* __restrict__ out,
                         int N, int K, int reluIn, int reluOut)
{
    int idx = blockIdx.x * blockDim.x + threadIdx.x;
    if (idx >= 32 * N) return;
    int b = idx / N, n = idx % N;
    float s = bias[n];
    const float* ip = in + b * K;
    const float* wp = w + n * K;
    for (int k = 0; k < K; k++) {
        float a = ip[k];
        if (reluIn) a = fmaxf(a, 0.f);
        s = fmaf(a, wp[k], s);
    }
    if (reluOut) s = fmaxf(s, 0.f);
    out[idx] = s;
}

// ---------------- host launcher ----------------
extern "C" void kernel_launch(void* const* d_in, const int* in_sizes, int n_in,
                              void* d_out, int out_size)
{
    const float* x     = (const float*)d_in[0];
    const float* w_in  = (const float*)d_in[1];
    const float* b_in  = (const float*)d_in[2];
    const float* w1    = (const float*)d_in[3];
    const float* b1    = (const float*)d_in[4];
    const float* w2    = (const float*)d_in[5];
    const float* b2    = (const float*)d_in[6];
    const float* w3    = (const float*)d_in[7];
    const float* b3    = (const float*)d_in[8];
    const float* w4    = (const float*)d_in[9];
    const float* b4    = (const float*)d_in[10];
    const float* w5    = (const float*)d_in[11];
    const float* b5    = (const float*)d_in[12];
    const float* wfc1  = (const float*)d_in[13];
    const float* bfc1  = (const float*)d_in[14];
    const float* wfc2  = (const float*)d_in[15];
    const float* bfc2  = (const float*)d_in[16];
    const float* wfc3  = (const float*)d_in[17];
    const float* bfc3  = (const float*)d_in[18];
    const float* wfc4  = (const float*)d_in[19];
    const float* bfc4  = (const float*)d_in[20];
    float* out = (float*)d_out;

    float *x1, *x2, *x3, *x4, *x5, *x6;
    float *wpin, *wp1, *wp2, *wp3, *wp4, *wp5;
    float *part, *h1, *h2, *h3, *phi, *trig;
    cudaGetSymbolAddress((void**)&x1, g_x1);
    cudaGetSymbolAddress((void**)&x2, g_x2);
    cudaGetSymbolAddress((void**)&x3, g_x3);
    cudaGetSymbolAddress((void**)&x4, g_x4);
    cudaGetSymbolAddress((void**)&x5, g_x5);
    cudaGetSymbolAddress((void**)&x6, g_x6);
    cudaGetSymbolAddress((void**)&wpin, g_wt_in);
    cudaGetSymbolAddress((void**)&wp1, g_wt1);
    cudaGetSymbolAddress((void**)&wp2, g_wt2);
    cudaGetSymbolAddress((void**)&wp3, g_wt3);
    cudaGetSymbolAddress((void**)&wp4, g_wt4);
    cudaGetSymbolAddress((void**)&wp5, g_wt5);
    cudaGetSymbolAddress((void**)&part, g_part);
    cudaGetSymbolAddress((void**)&h1, g_h1);
    cudaGetSymbolAddress((void**)&h2, g_h2);
    cudaGetSymbolAddress((void**)&h3, g_h3);
    cudaGetSymbolAddress((void**)&phi, g_phi);
    cudaGetSymbolAddress((void**)&trig, g_trig);

    // dynamic smem sizes (float2 elements)
    const int smem_in  = (1 * 8 * 36 + 1 * 25 * 32) * 8;     //  8704
    const int smem_64  = (8 * 8 * 36 + 8 * 25 * 32) * 8;     // 69632
    const int smem_128 = (4 * 6 * 36 + 4 * 25 * 64) * 8;     // 58112
    cudaFuncSetAttribute(conv5x5_p<64, 32, 4, 8>,
                         cudaFuncAttributeMaxDynamicSharedMemorySize, smem_64);
    cudaFuncSetAttribute(conv5x5_p<128, 64, 2, 4>,
                         cudaFuncAttributeMaxDynamicSharedMemorySize, smem_128);

    // tables + weight packing
    init_tables<<<1, 1>>>(phi, trig);
    pack_w<<<(1 * 25 * 32 + 255) / 256, 256>>>(w_in, (float2*)wpin, 64, 1);
    pack_w<<<(64 * 25 * 32 + 255) / 256, 256>>>(w1, (float2*)wp1, 64, 64);
    pack_w<<<(64 * 25 * 32 + 255) / 256, 256>>>(w2, (float2*)wp2, 64, 64);
    pack_w<<<(64 * 25 * 32 + 255) / 256, 256>>>(w3, (float2*)wp3, 64, 64);
    pack_w<<<(64 * 25 * 32 + 255) / 256, 256>>>(w4, (float2*)wp4, 64, 64);
    pack_w<<<(128 * 25 * 64 + 255) / 256, 256>>>(w5, (float2*)wp5, 128, 128);

    dim3 g64(6, 6, B);     // xtiles=6, ytiles=ceil(21/4)=6
    dim3 g128(6, 11, B);   // ytiles=ceil(21/2)=11

    // conv chain; concat fused via dual-write epilogues
    conv5x5_p<1, 32, 4, 1><<<g64, 128, smem_in>>>(x, (float2*)wpin, b_in, x1, 64,
                                                  nullptr, 0, 0);
    conv5x5_p<64, 32, 4, 8><<<g64, 128, smem_64>>>(x1, (float2*)wp1, b1, x2, 64,
                                                   x6, 192, 128);   // x2 -> x6[128:192]
    conv5x5_p<64, 32, 4, 8><<<g64, 128, smem_64>>>(x2, (float2*)wp2, b2, x3, 64,
                                                   x5, 128, 64);    // x3 -> x5[64:128]
    conv5x5_p<64, 32, 4, 8><<<g64, 128, smem_64>>>(x3, (float2*)wp3, b3, x4, 64,
                                                   nullptr, 0, 0);
    conv5x5_p<64, 32, 4, 8><<<g64, 128, smem_64>>>(x4, (float2*)wp4, b4, x5, 128,
                                                   nullptr, 0, 0);  // x5[0:64]
    conv5x5_p<128, 64, 2, 4><<<g128, 128, smem_128>>>(x5, (float2*)wp5, b5, x6, 192,
                                                      nullptr, 0, 0); // x6[0:128]

    // residual filters (closed-form projections; no FFT)
    filter_lat<<<(B * 192 * W + 255) / 256, 256>>>(x6, phi);
    filter_lon<<<(B * 192 * H * 32 + 255) / 256, 256>>>(x6, trig);

    // FC stack
    fc1_partial<<<dim3(NSPLIT, 4), 128>>>(x6, wfc1, part);
    fc1_reduce<<<64, 256>>>(part, bfc1, h1);
    fc_small<<<(32 * 200 + 255) / 256, 256>>>(h1, wfc2, bfc2, h2, 200, 500, 1, 1);
    fc_small<<<(32 * 50 + 255) / 256, 256>>>(h2, wfc3, bfc3, h3, 50, 200, 0, 1);
    fc_small<<<1, 64>>>(h3, wfc4, bfc4, out, 2, 50, 0, 0);
}